// round 13
// baseline (speedup 1.0000x reference)
#include <cuda_runtime.h>
#include <math.h>

#define NNODES 50000
#define NEDGES 800000
#define NGRAPHS 64
#define NLOCS 50

// ---------------- device scratch ----------------
__device__ float g_h[(size_t)NNODES * 144];    // GEMM out (features + es + ed)
__device__ float g_act[(size_t)NNODES * 132];  // gather out / next GEMM in
__device__ float g_Wp0[8 * 144];
__device__ float g_Wp1[132 * 144];
__device__ float g_Wp2[132 * 132];
__device__ int g_deg[NNODES];
__device__ int g_cur[NNODES];
__device__ int g_rowptr[NNODES + 1];
__device__ int g_col[NEDGES];
__device__ int g_bsum[64];
__device__ int g_boff[64];
__device__ float g_pool[NGRAPHS * 128];
__device__ int g_cnt[NGRAPHS];

__device__ __forceinline__ float leakyf(float v) { return v > 0.f ? v : 0.2f * v; }

// ---- f32x2 packed math (Blackwell FFMA2) ----
__device__ __forceinline__ unsigned long long ffma2(unsigned long long a, unsigned long long b,
                                                    unsigned long long c) {
    unsigned long long d;
    asm("fma.rn.f32x2 %0, %1, %2, %3;" : "=l"(d) : "l"(a), "l"(b), "l"(c));
    return d;
}
__device__ __forceinline__ unsigned long long dupf2(float x) {
    unsigned long long d;
    asm("mov.b64 %0, {%1, %1};" : "=l"(d) : "f"(x));
    return d;
}
__device__ __forceinline__ void unpackf2(unsigned long long v, float& lo, float& hi) {
    asm("mov.b64 {%0, %1}, %2;" : "=f"(lo), "=f"(hi) : "l"(v));
}

// ---------------- weight packing (fold attention dots into GEMM) ----------------
__global__ void pack_weights(const float* __restrict__ W, const float* __restrict__ avs,
                             const float* __restrict__ avd, int which,
                             int K, int M, int MP, int KP, int H, int O, int ES, int ED) {
    float* Wp = (which == 0) ? g_Wp0 : (which == 1) ? g_Wp1 : g_Wp2;
    int i = blockIdx.x * blockDim.x + threadIdx.x;
    if (i >= KP * MP) return;
    int k = i / MP, j = i % MP;
    float v = 0.f;
    if (k < K) {
        if (j < M) {
            v = W[k * M + j];
        } else if (j >= ES && j < ES + H) {
            int h = j - ES; float s = 0.f;
            for (int o = 0; o < O; o++) s += W[k * M + h * O + o] * avs[h * O + o];
            v = s;
        } else if (j >= ED && j < ED + H) {
            int h = j - ED; float s = 0.f;
            for (int o = 0; o < O; o++) s += W[k * M + h * O + o] * avd[h * O + o];
            v = s;
        }
    }
    Wp[i] = v;
}

// ---------------- CSR build ----------------
__global__ void zero_aux() {
    int i = blockIdx.x * blockDim.x + threadIdx.x;
    if (i < NNODES) { g_deg[i] = 0; g_cur[i] = 0; }
    if (i < NGRAPHS * 128) g_pool[i] = 0.f;
    if (i < NGRAPHS) g_cnt[i] = 0;
}

__global__ void hist_kernel(const int* __restrict__ dstv) {
    int i = blockIdx.x * blockDim.x + threadIdx.x;
    if (i < NEDGES) atomicAdd(&g_deg[dstv[i]], 1);
}

// 3-kernel parallel exclusive scan of degrees -> rowptr
__global__ void scan_blocks() {
    __shared__ int buf[1024];
    int t = threadIdx.x;
    int idx = blockIdx.x * 1024 + t;
    int v = (idx < NNODES) ? g_deg[idx] : 0;
    buf[t] = v;
    __syncthreads();
    for (int off = 1; off < 1024; off <<= 1) {
        int a = (t >= off) ? buf[t - off] : 0;
        __syncthreads();
        buf[t] += a;
        __syncthreads();
    }
    if (idx < NNODES) g_rowptr[idx + 1] = buf[t];
    if (t == 1023) g_bsum[blockIdx.x] = buf[1023];
}

__global__ void scan_tops(int nblk) {
    __shared__ int buf[64];
    int t = threadIdx.x;
    int v = (t < nblk) ? g_bsum[t] : 0;
    buf[t] = v;
    __syncthreads();
    for (int off = 1; off < 64; off <<= 1) {
        int a = (t >= off) ? buf[t - off] : 0;
        __syncthreads();
        buf[t] += a;
        __syncthreads();
    }
    if (t < nblk) g_boff[t] = buf[t] - v;  // exclusive
}

__global__ void scan_add() {
    int t = threadIdx.x;
    int idx = blockIdx.x * 1024 + t;
    if (idx < NNODES) g_rowptr[idx + 1] += g_boff[blockIdx.x];
    if (idx == 0) g_rowptr[0] = 0;
}

__global__ void fill_kernel(const int* __restrict__ srcv, const int* __restrict__ dstv) {
    int i = blockIdx.x * blockDim.x + threadIdx.x;
    if (i < NEDGES) {
        int d = dstv[i];
        int p = atomicAdd(&g_cur[d], 1);
        g_col[g_rowptr[d] + p] = srcv[i];
    }
}

// ---------------- layer-0 GEMM (K=6) ----------------
__global__ void gemm0_kernel(const float* __restrict__ x) {
    int n = blockIdx.x;
    int j = threadIdx.x;
    float xr[6];
#pragma unroll
    for (int k = 0; k < 6; k++) xr[k] = __ldg(&x[n * 6 + k]);
    if (j < 144) {
        float a = 0.f;
#pragma unroll
        for (int k = 0; k < 6; k++) a += xr[k] * g_Wp0[k * 144 + j];
        g_h[(size_t)n * 144 + j] = a;
    }
}

// ---------------- tiled GEMM with f32x2: g_act[N,132] @ Wp[132,MP] -> g_h[N,MP] ----------------
template <int MP>
__global__ void gemm_tiled(int wsel, int N) {
    constexpr int KP = 132;
    constexpr int TXN = MP / 4;
    constexpr int NTH = TXN * 8;
    __shared__ float xs[KP][68];  // transposed A tile, row stride 272B
    const float* Wp = (wsel == 1) ? g_Wp1 : g_Wp2;
    const float4* W4 = (const float4*)Wp;
    int tx = threadIdx.x, ty = threadIdx.y;
    int t = ty * TXN + tx;
    int n0 = blockIdx.x * 64;
    for (int i = t; i < 64 * 33; i += NTH) {
        int n = i / 33, k4 = i % 33;
        int gn = n0 + n;
        float4 v = make_float4(0.f, 0.f, 0.f, 0.f);
        if (gn < N) v = __ldg((const float4*)(g_act + (size_t)gn * 132 + k4 * 4));
        xs[k4 * 4 + 0][n] = v.x;
        xs[k4 * 4 + 1][n] = v.y;
        xs[k4 * 4 + 2][n] = v.z;
        xs[k4 * 4 + 3][n] = v.w;
    }
    __syncthreads();
    unsigned long long acc2[4][4];  // [node-pair][col]
#pragma unroll
    for (int p = 0; p < 4; p++)
#pragma unroll
        for (int c = 0; c < 4; c++) acc2[p][c] = 0ull;
    int nb = ty * 8;
#pragma unroll 2
    for (int k = 0; k < KP; k++) {
        float4 w = __ldg(&W4[k * TXN + tx]);
        unsigned long long wd0 = dupf2(w.x), wd1 = dupf2(w.y), wd2 = dupf2(w.z), wd3 = dupf2(w.w);
        const unsigned long long* xr = (const unsigned long long*)&xs[k][nb];
        unsigned long long x0 = xr[0], x1 = xr[1], x2 = xr[2], x3 = xr[3];
        acc2[0][0] = ffma2(x0, wd0, acc2[0][0]);
        acc2[0][1] = ffma2(x0, wd1, acc2[0][1]);
        acc2[0][2] = ffma2(x0, wd2, acc2[0][2]);
        acc2[0][3] = ffma2(x0, wd3, acc2[0][3]);
        acc2[1][0] = ffma2(x1, wd0, acc2[1][0]);
        acc2[1][1] = ffma2(x1, wd1, acc2[1][1]);
        acc2[1][2] = ffma2(x1, wd2, acc2[1][2]);
        acc2[1][3] = ffma2(x1, wd3, acc2[1][3]);
        acc2[2][0] = ffma2(x2, wd0, acc2[2][0]);
        acc2[2][1] = ffma2(x2, wd1, acc2[2][1]);
        acc2[2][2] = ffma2(x2, wd2, acc2[2][2]);
        acc2[2][3] = ffma2(x2, wd3, acc2[2][3]);
        acc2[3][0] = ffma2(x3, wd0, acc2[3][0]);
        acc2[3][1] = ffma2(x3, wd1, acc2[3][1]);
        acc2[3][2] = ffma2(x3, wd2, acc2[3][2]);
        acc2[3][3] = ffma2(x3, wd3, acc2[3][3]);
    }
#pragma unroll
    for (int p = 0; p < 4; p++) {
        float lo0, hi0, lo1, hi1, lo2, hi2, lo3, hi3;
        unpackf2(acc2[p][0], lo0, hi0);
        unpackf2(acc2[p][1], lo1, hi1);
        unpackf2(acc2[p][2], lo2, hi2);
        unpackf2(acc2[p][3], lo3, hi3);
        int gnl = n0 + nb + 2 * p;
        int gnh = gnl + 1;
        if (gnl < N) {
            float4 o = make_float4(lo0, lo1, lo2, lo3);
            *(float4*)(g_h + (size_t)gnl * MP + tx * 4) = o;
        }
        if (gnh < N) {
            float4 o = make_float4(hi0, hi1, hi2, hi3);
            *(float4*)(g_h + (size_t)gnh * MP + tx * 4) = o;
        }
    }
}

// ---------------- GAT gather v3: single pass (no segment max; softmax shift-invariant,
// logits tiny), float4 feature loads: lane owns features 4*lane..4*lane+3 (+lane0 extra for M=129).
template <int H, int O, int M, int SIN, int ESOFF, int EDOFF, int SOUT, int ACT, int FUSEPOOL>
__global__ void gather_kernel(const float* __restrict__ bias, const int* __restrict__ batch) {
    int gw = (blockIdx.x * blockDim.x + threadIdx.x) >> 5;
    int lane = threadIdx.x & 31;
    if (gw >= NNODES) return;
    int n = gw;
    const float* hn = g_h + (size_t)n * SIN;
    // per-component head selection (compile-time friendly)
    int hc0 = 0, hc1 = 0, hc2 = 0, hc3 = 0;
    if (H > 1) {
        hc0 = (4 * lane + 0) / O;
        hc1 = (4 * lane + 1) / O;
        hc2 = (4 * lane + 2) / O;
        hc3 = (4 * lane + 3) / O;
    }
    constexpr bool EXTRA = (M == 4 * 32 + 1);  // feature index 128 handled by lane 0
    float edv0 = __ldg(&hn[EDOFF]), edv1 = 0.f, edv2 = 0.f;
    float es0 = __ldg(&hn[ESOFF]), es1 = 0.f, es2 = 0.f;
    if (H > 1) { edv1 = __ldg(&hn[EDOFF + 1]); es1 = __ldg(&hn[ESOFF + 1]); }
    if (H > 2) { edv2 = __ldg(&hn[EDOFF + 2]); es2 = __ldg(&hn[ESOFF + 2]); }
    // self-loop weight (no max subtraction: exp(e) directly)
    float w0s = __expf(leakyf(es0 + edv0));
    float w1s = (H > 1) ? __expf(leakyf(es1 + edv1)) : w0s;
    float w2s = (H > 2) ? __expf(leakyf(es2 + edv2)) : w1s;
    float z0 = w0s, z1 = w1s, z2 = w2s;
    float4 hv = __ldg((const float4*)(hn) + lane);
    float4 acc;
    {
        float wa = (H == 1) ? w0s : (hc0 == 0 ? w0s : (hc0 == 1 ? w1s : w2s));
        float wb = (H == 1) ? w0s : (hc1 == 0 ? w0s : (hc1 == 1 ? w1s : w2s));
        float wc = (H == 1) ? w0s : (hc2 == 0 ? w0s : (hc2 == 1 ? w1s : w2s));
        float wd = (H == 1) ? w0s : (hc3 == 0 ? w0s : (hc3 == 1 ? w1s : w2s));
        acc = make_float4(wa * hv.x, wb * hv.y, wc * hv.z, wd * hv.w);
    }
    float accx = 0.f;
    if (EXTRA && lane == 0) accx = w2s * __ldg(&hn[128]);
    int beg = __ldg(&g_rowptr[n]);
    int end = __ldg(&g_rowptr[n + 1]);
    int e = beg;
    int s_next = (e < end) ? __ldg(&g_col[e]) : 0;
    while (e < end) {
        int s = s_next;
        if (e + 1 < end) s_next = __ldg(&g_col[e + 1]);
        const float* hs = g_h + (size_t)s * SIN;
        float4 eq = __ldg((const float4*)(hs + ESOFF));
        float4 f = __ldg((const float4*)(hs) + lane);
        float fx = (EXTRA && lane == 0) ? __ldg(&hs[128]) : 0.f;
        float w0 = __expf(leakyf(eq.x + edv0)); z0 += w0;
        float w1 = w0, w2 = w0;
        if (H > 1) { w1 = __expf(leakyf(eq.y + edv1)); z1 += w1; }
        if (H > 2) { w2 = __expf(leakyf(eq.z + edv2)); z2 += w2; }
        float wa = (H == 1) ? w0 : (hc0 == 0 ? w0 : (hc0 == 1 ? w1 : w2));
        float wb = (H == 1) ? w0 : (hc1 == 0 ? w0 : (hc1 == 1 ? w1 : w2));
        float wc = (H == 1) ? w0 : (hc2 == 0 ? w0 : (hc2 == 1 ? w1 : w2));
        float wd = (H == 1) ? w0 : (hc3 == 0 ? w0 : (hc3 == 1 ? w1 : w2));
        acc.x += wa * f.x;
        acc.y += wb * f.y;
        acc.z += wc * f.z;
        acc.w += wd * f.w;
        if (EXTRA && lane == 0) accx += w2 * fx;
        e++;
    }
    float za = (H == 1) ? z0 : (hc0 == 0 ? z0 : (hc0 == 1 ? z1 : z2));
    float zb = (H == 1) ? z0 : (hc1 == 0 ? z0 : (hc1 == 1 ? z1 : z2));
    float zc = (H == 1) ? z0 : (hc2 == 0 ? z0 : (hc2 == 1 ? z1 : z2));
    float zd = (H == 1) ? z0 : (hc3 == 0 ? z0 : (hc3 == 1 ? z1 : z2));
    float4 bv = __ldg((const float4*)(bias) + lane);
    float4 v;
    v.x = acc.x / (za + 1e-16f) + bv.x;
    v.y = acc.y / (zb + 1e-16f) + bv.y;
    v.z = acc.z / (zc + 1e-16f) + bv.z;
    v.w = acc.w / (zd + 1e-16f) + bv.w;
    if (ACT) {
        v.x = leakyf(v.x); v.y = leakyf(v.y); v.z = leakyf(v.z); v.w = leakyf(v.w);
    }
    if (!FUSEPOOL) {
        *(float4*)(g_act + (size_t)n * SOUT + lane * 4) = v;
        if (EXTRA && lane == 0) {
            float vx = accx / (z2 + 1e-16f) + __ldg(&bias[128]);
            if (ACT) vx = leakyf(vx);
            g_act[(size_t)n * SOUT + 128] = vx;
        }
    } else {
        // layer 2 (H==1, M==128): float4 layout already matches pool — direct vector atomic
        int b = __ldg(&batch[n]);
        atomicAdd(reinterpret_cast<float4*>(g_pool + b * 128) + lane, v);
        if (lane == 0) atomicAdd(&g_cnt[b], 1);
    }
}

__global__ void finalize_kernel(float* __restrict__ out) {
    int b = blockIdx.x, j = threadIdx.x;  // 256 threads
    if (j < 128) {
        int c = g_cnt[b];
        float cf = (float)(c > 1 ? c : 1);
        out[b * 256 + j] = g_pool[b * 128 + j] / cf;
    } else {
        out[b * 256 + j] = 0.f;  // zero loc half for atomic accumulation
    }
}

// ---------------- location MLP: 4 blocks per graph, atomic accumulate ----------------
__global__ void locmlp_kernel(const float* __restrict__ loc, const float* __restrict__ Wl1,
                              const float* __restrict__ bl1, const float* __restrict__ Wl2,
                              const float* __restrict__ bl2, float* __restrict__ out) {
    int b = blockIdx.x >> 2;
    int part = blockIdx.x & 3;
    int t = threadIdx.x;  // 256
    int lbeg = part * 12 + min(part, 2);
    int lend = (part + 1) * 12 + min(part + 1, 2);
    __shared__ float hid[256];
    float w1a = __ldg(&Wl1[t]), w1b = __ldg(&Wl1[256 + t]), b1v = __ldg(&bl1[t]);
    float accv = 0.f;
    for (int l = lbeg; l < lend; l++) {
        float lx = __ldg(&loc[(b * NLOCS + l) * 2 + 0]);
        float ly = __ldg(&loc[(b * NLOCS + l) * 2 + 1]);
        float hv = tanhf(lx * w1a + ly * w1b + b1v);
        __syncthreads();
        hid[t] = hv;
        __syncthreads();
        if (t < 128) {
            float s = 0.f;
#pragma unroll 8
            for (int k = 0; k < 256; k++) s += hid[k] * __ldg(&Wl2[k * 128 + t]);
            accv += s;
        }
    }
    if (t < 128) {
        float v = accv * (1.f / (float)NLOCS);
        if (part == 0) v += __ldg(&bl2[t]);
        atomicAdd(&out[b * 256 + 128 + t], v);
    }
}

// ---------------- launch ----------------
extern "C" void kernel_launch(void* const* d_in, const int* in_sizes, int n_in,
                              void* d_out, int out_size) {
    const float* x   = (const float*)d_in[0];
    const float* loc = (const float*)d_in[1];
    const int* ei    = (const int*)d_in[2];
    const int* batch = (const int*)d_in[3];
    const float* W0  = (const float*)d_in[4];
    const float* as0 = (const float*)d_in[5];
    const float* ad0 = (const float*)d_in[6];
    const float* b0  = (const float*)d_in[7];
    const float* W1  = (const float*)d_in[8];
    const float* as1 = (const float*)d_in[9];
    const float* ad1 = (const float*)d_in[10];
    const float* b1  = (const float*)d_in[11];
    const float* W2  = (const float*)d_in[12];
    const float* as2 = (const float*)d_in[13];
    const float* ad2 = (const float*)d_in[14];
    const float* b2  = (const float*)d_in[15];
    const float* Wl1 = (const float*)d_in[16];
    const float* bl1 = (const float*)d_in[17];
    const float* Wl2 = (const float*)d_in[18];
    const float* bl2 = (const float*)d_in[19];
    float* out = (float*)d_out;
    const int* srcv = ei;
    const int* dstv = ei + NEDGES;

    pack_weights<<<(8 * 144 + 255) / 256, 256>>>(W0, as0, ad0, 0, 6, 129, 144, 8, 3, 43, 132, 136);
    pack_weights<<<(132 * 144 + 255) / 256, 256>>>(W1, as1, ad1, 1, 129, 129, 144, 132, 3, 43, 132, 136);
    pack_weights<<<(132 * 132 + 255) / 256, 256>>>(W2, as2, ad2, 2, 129, 128, 132, 132, 1, 128, 128, 129);

    int nscan = (NNODES + 1023) / 1024;  // 49
    zero_aux<<<(NNODES + 255) / 256, 256>>>();
    hist_kernel<<<(NEDGES + 255) / 256, 256>>>(dstv);
    scan_blocks<<<nscan, 1024>>>();
    scan_tops<<<1, 64>>>(nscan);
    scan_add<<<nscan, 1024>>>();
    fill_kernel<<<(NEDGES + 255) / 256, 256>>>(srcv, dstv);

    int gatherBlocks = (NNODES + 7) / 8;
    int gemmBlocks = (NNODES + 63) / 64;

    gemm0_kernel<<<NNODES, 160>>>(x);
    gather_kernel<3, 43, 129, 144, 132, 136, 132, 1, 0><<<gatherBlocks, 256>>>(b0, batch);
    gemm_tiled<144><<<gemmBlocks, dim3(36, 8)>>>(1, NNODES);
    gather_kernel<3, 43, 129, 144, 132, 136, 132, 1, 0><<<gatherBlocks, 256>>>(b1, batch);
    gemm_tiled<132><<<gemmBlocks, dim3(33, 8)>>>(2, NNODES);
    gather_kernel<1, 128, 128, 132, 128, 129, 128, 0, 1><<<gatherBlocks, 256>>>(b2, batch);

    finalize_kernel<<<64, 256>>>(out);
    locmlp_kernel<<<256, 256>>>(loc, Wl1, bl1, Wl2, bl2, out);
}

// round 17
// speedup vs baseline: 1.1511x; 1.1511x over previous
#include <cuda_runtime.h>
#include <math.h>

#define NNODES 50000
#define NEDGES 800000
#define NGRAPHS 64
#define NLOCS 50

// ---------------- device scratch ----------------
__device__ float g_h[(size_t)NNODES * 144];    // GEMM out (features + es + ed)
__device__ float g_act[(size_t)NNODES * 132];  // gather out / next GEMM in
__device__ float g_Wp0[8 * 144];
__device__ float g_Wp1[132 * 144];
__device__ float g_Wp2[132 * 132];
__device__ int g_deg[NNODES];
__device__ int g_cur[NNODES];
__device__ int g_rowptr[NNODES + 1];
__device__ int g_col[NEDGES];
__device__ int g_bsum[64];
__device__ int g_boff[64];
__device__ float g_pool[NGRAPHS * 128];
__device__ int g_cnt[NGRAPHS];

__device__ __forceinline__ float leakyf(float v) { return v > 0.f ? v : 0.2f * v; }

// ---- f32x2 packed math (Blackwell FFMA2) ----
__device__ __forceinline__ unsigned long long ffma2(unsigned long long a, unsigned long long b,
                                                    unsigned long long c) {
    unsigned long long d;
    asm("fma.rn.f32x2 %0, %1, %2, %3;" : "=l"(d) : "l"(a), "l"(b), "l"(c));
    return d;
}
__device__ __forceinline__ unsigned long long dupf2(float x) {
    unsigned long long d;
    asm("mov.b64 %0, {%1, %1};" : "=l"(d) : "f"(x));
    return d;
}
__device__ __forceinline__ void unpackf2(unsigned long long v, float& lo, float& hi) {
    asm("mov.b64 {%0, %1}, %2;" : "=f"(lo), "=f"(hi) : "l"(v));
}

// ---------------- weight packing (fold attention dots into GEMM) ----------------
__global__ void pack_weights(const float* __restrict__ W, const float* __restrict__ avs,
                             const float* __restrict__ avd, int which,
                             int K, int M, int MP, int KP, int H, int O, int ES, int ED) {
    float* Wp = (which == 0) ? g_Wp0 : (which == 1) ? g_Wp1 : g_Wp2;
    int i = blockIdx.x * blockDim.x + threadIdx.x;
    if (i >= KP * MP) return;
    int k = i / MP, j = i % MP;
    float v = 0.f;
    if (k < K) {
        if (j < M) {
            v = W[k * M + j];
        } else if (j >= ES && j < ES + H) {
            int h = j - ES; float s = 0.f;
            for (int o = 0; o < O; o++) s += W[k * M + h * O + o] * avs[h * O + o];
            v = s;
        } else if (j >= ED && j < ED + H) {
            int h = j - ED; float s = 0.f;
            for (int o = 0; o < O; o++) s += W[k * M + h * O + o] * avd[h * O + o];
            v = s;
        }
    }
    Wp[i] = v;
}

// ---------------- CSR build ----------------
__global__ void zero_aux() {
    int i = blockIdx.x * blockDim.x + threadIdx.x;
    if (i < NNODES) { g_deg[i] = 0; g_cur[i] = 0; }
    if (i < NGRAPHS * 128) g_pool[i] = 0.f;
    if (i < NGRAPHS) g_cnt[i] = 0;
}

__global__ void hist_kernel(const int* __restrict__ dstv) {
    int i = blockIdx.x * blockDim.x + threadIdx.x;
    if (i < NEDGES) atomicAdd(&g_deg[dstv[i]], 1);
}

// 3-kernel parallel exclusive scan of degrees -> rowptr
__global__ void scan_blocks() {
    __shared__ int buf[1024];
    int t = threadIdx.x;
    int idx = blockIdx.x * 1024 + t;
    int v = (idx < NNODES) ? g_deg[idx] : 0;
    buf[t] = v;
    __syncthreads();
    for (int off = 1; off < 1024; off <<= 1) {
        int a = (t >= off) ? buf[t - off] : 0;
        __syncthreads();
        buf[t] += a;
        __syncthreads();
    }
    if (idx < NNODES) g_rowptr[idx + 1] = buf[t];
    if (t == 1023) g_bsum[blockIdx.x] = buf[1023];
}

__global__ void scan_tops(int nblk) {
    __shared__ int buf[64];
    int t = threadIdx.x;
    int v = (t < nblk) ? g_bsum[t] : 0;
    buf[t] = v;
    __syncthreads();
    for (int off = 1; off < 64; off <<= 1) {
        int a = (t >= off) ? buf[t - off] : 0;
        __syncthreads();
        buf[t] += a;
        __syncthreads();
    }
    if (t < nblk) g_boff[t] = buf[t] - v;  // exclusive
}

__global__ void scan_add() {
    int t = threadIdx.x;
    int idx = blockIdx.x * 1024 + t;
    if (idx < NNODES) g_rowptr[idx + 1] += g_boff[blockIdx.x];
    if (idx == 0) g_rowptr[0] = 0;
}

__global__ void fill_kernel(const int* __restrict__ srcv, const int* __restrict__ dstv) {
    int i = blockIdx.x * blockDim.x + threadIdx.x;
    if (i < NEDGES) {
        int d = dstv[i];
        int p = atomicAdd(&g_cur[d], 1);
        g_col[g_rowptr[d] + p] = srcv[i];
    }
}

// ---------------- layer-0 GEMM (K=6) ----------------
__global__ void gemm0_kernel(const float* __restrict__ x) {
    int n = blockIdx.x;
    int j = threadIdx.x;
    float xr[6];
#pragma unroll
    for (int k = 0; k < 6; k++) xr[k] = __ldg(&x[n * 6 + k]);
    if (j < 144) {
        float a = 0.f;
#pragma unroll
        for (int k = 0; k < 6; k++) a += xr[k] * g_Wp0[k * 144 + j];
        g_h[(size_t)n * 144 + j] = a;
    }
}

// ---------------- tiled GEMM with f32x2: g_act[N,132] @ Wp[132,MP] -> g_h[N,MP] ----------------
template <int MP>
__global__ void gemm_tiled(int wsel, int N) {
    constexpr int KP = 132;
    constexpr int TXN = MP / 4;
    constexpr int NTH = TXN * 8;
    __shared__ float xs[KP][68];  // transposed A tile, row stride 272B
    const float* Wp = (wsel == 1) ? g_Wp1 : g_Wp2;
    const float4* W4 = (const float4*)Wp;
    int tx = threadIdx.x, ty = threadIdx.y;
    int t = ty * TXN + tx;
    int n0 = blockIdx.x * 64;
    for (int i = t; i < 64 * 33; i += NTH) {
        int n = i / 33, k4 = i % 33;
        int gn = n0 + n;
        float4 v = make_float4(0.f, 0.f, 0.f, 0.f);
        if (gn < N) v = __ldg((const float4*)(g_act + (size_t)gn * 132 + k4 * 4));
        xs[k4 * 4 + 0][n] = v.x;
        xs[k4 * 4 + 1][n] = v.y;
        xs[k4 * 4 + 2][n] = v.z;
        xs[k4 * 4 + 3][n] = v.w;
    }
    __syncthreads();
    unsigned long long acc2[4][4];  // [node-pair][col]
#pragma unroll
    for (int p = 0; p < 4; p++)
#pragma unroll
        for (int c = 0; c < 4; c++) acc2[p][c] = 0ull;
    int nb = ty * 8;
#pragma unroll 2
    for (int k = 0; k < KP; k++) {
        float4 w = __ldg(&W4[k * TXN + tx]);
        unsigned long long wd0 = dupf2(w.x), wd1 = dupf2(w.y), wd2 = dupf2(w.z), wd3 = dupf2(w.w);
        const unsigned long long* xr = (const unsigned long long*)&xs[k][nb];
        unsigned long long x0 = xr[0], x1 = xr[1], x2 = xr[2], x3 = xr[3];
        acc2[0][0] = ffma2(x0, wd0, acc2[0][0]);
        acc2[0][1] = ffma2(x0, wd1, acc2[0][1]);
        acc2[0][2] = ffma2(x0, wd2, acc2[0][2]);
        acc2[0][3] = ffma2(x0, wd3, acc2[0][3]);
        acc2[1][0] = ffma2(x1, wd0, acc2[1][0]);
        acc2[1][1] = ffma2(x1, wd1, acc2[1][1]);
        acc2[1][2] = ffma2(x1, wd2, acc2[1][2]);
        acc2[1][3] = ffma2(x1, wd3, acc2[1][3]);
        acc2[2][0] = ffma2(x2, wd0, acc2[2][0]);
        acc2[2][1] = ffma2(x2, wd1, acc2[2][1]);
        acc2[2][2] = ffma2(x2, wd2, acc2[2][2]);
        acc2[2][3] = ffma2(x2, wd3, acc2[2][3]);
        acc2[3][0] = ffma2(x3, wd0, acc2[3][0]);
        acc2[3][1] = ffma2(x3, wd1, acc2[3][1]);
        acc2[3][2] = ffma2(x3, wd2, acc2[3][2]);
        acc2[3][3] = ffma2(x3, wd3, acc2[3][3]);
    }
#pragma unroll
    for (int p = 0; p < 4; p++) {
        float lo0, hi0, lo1, hi1, lo2, hi2, lo3, hi3;
        unpackf2(acc2[p][0], lo0, hi0);
        unpackf2(acc2[p][1], lo1, hi1);
        unpackf2(acc2[p][2], lo2, hi2);
        unpackf2(acc2[p][3], lo3, hi3);
        int gnl = n0 + nb + 2 * p;
        int gnh = gnl + 1;
        if (gnl < N) {
            float4 o = make_float4(lo0, lo1, lo2, lo3);
            *(float4*)(g_h + (size_t)gnl * MP + tx * 4) = o;
        }
        if (gnh < N) {
            float4 o = make_float4(hi0, hi1, hi2, hi3);
            *(float4*)(g_h + (size_t)gnh * MP + tx * 4) = o;
        }
    }
}

// ---------------- GAT gather (R9 structure + pass-2 unroll-2): warp per dst node ----------------
// pass1 (lanes over edges): segment max — ALSO serves as L1 prefetch of g_col + eq lines.
// pass2 (lanes over features): unrolled by 2 edges, all loads staged before dependent exp/FMA.
template <int H, int O, int M, int SIN, int ESOFF, int EDOFF, int SOUT, int ACT, int FUSEPOOL>
__global__ void gather_kernel(const float* __restrict__ bias, const int* __restrict__ batch) {
    int gw = (blockIdx.x * blockDim.x + threadIdx.x) >> 5;
    int lane = threadIdx.x & 31;
    int wid = threadIdx.x >> 5;
    __shared__ float sh[8][128];
    if (gw >= NNODES) return;
    int n = gw;
    const float* hn = g_h + (size_t)n * SIN;
    float edv[3], esn[3], selfe[3], mx[3];
#pragma unroll
    for (int h = 0; h < H; h++) {
        edv[h] = __ldg(&hn[EDOFF + h]);
        esn[h] = __ldg(&hn[ESOFF + h]);
        selfe[h] = leakyf(esn[h] + edv[h]);
        mx[h] = selfe[h];
    }
    int beg = __ldg(&g_rowptr[n]);
    int end = __ldg(&g_rowptr[n + 1]);
    // pass 1: max over in-edges (lanes parallel over edges; prefetches col+eq into L1)
    for (int e = beg + lane; e < end; e += 32) {
        int s = __ldg(&g_col[e]);
        float4 eq = __ldg((const float4*)(g_h + (size_t)s * SIN + ESOFF));
        mx[0] = fmaxf(mx[0], leakyf(eq.x + edv[0]));
        if (H > 1) mx[1] = fmaxf(mx[1], leakyf(eq.y + edv[1]));
        if (H > 2) mx[2] = fmaxf(mx[2], leakyf(eq.z + edv[2]));
    }
#pragma unroll
    for (int h = 0; h < H; h++)
#pragma unroll
        for (int o = 16; o > 0; o >>= 1) mx[h] = fmaxf(mx[h], __shfl_xor_sync(0xffffffffu, mx[h], o));
    // pass 2 init: self-loop
    constexpr int NI = (M + 31) / 32;
    float z[3] = {0.f, 0.f, 0.f};
    float w0s, w1s = 0.f, w2s = 0.f;
    w0s = __expf(selfe[0] - mx[0]); z[0] = w0s;
    if (H > 1) { w1s = __expf(selfe[1] - mx[1]); z[1] = w1s; }
    if (H > 2) { w2s = __expf(selfe[2] - mx[2]); z[2] = w2s; }
    float acc[NI];
#pragma unroll
    for (int i = 0; i < NI; i++) {
        int j = lane + 32 * i;
        if (j < M) {
            int hdi = j / O;
            float ws = (H == 1) ? w0s : (hdi == 0 ? w0s : (hdi == 1 ? w1s : w2s));
            acc[i] = ws * __ldg(&hn[j]);
        } else acc[i] = 0.f;
    }
    // pass 2 main: unroll-2 with staged loads (same access pattern as R9, reordered issue)
    int e = beg;
    for (; e + 1 < end; e += 2) {
        int sA = __ldg(&g_col[e]);
        int sB = __ldg(&g_col[e + 1]);
        const float* hsA = g_h + (size_t)sA * SIN;
        const float* hsB = g_h + (size_t)sB * SIN;
        float4 eqA = __ldg((const float4*)(hsA + ESOFF));
        float4 eqB = __ldg((const float4*)(hsB + ESOFF));
        float fA[NI], fB[NI];
#pragma unroll
        for (int i = 0; i < NI; i++) {
            int j = lane + 32 * i;
            if (j < M) {
                fA[i] = __ldg(&hsA[j]);
                fB[i] = __ldg(&hsB[j]);
            }
        }
        float wA0 = __expf(leakyf(eqA.x + edv[0]) - mx[0]); z[0] += wA0;
        float wA1 = wA0, wA2 = wA0;
        if (H > 1) { wA1 = __expf(leakyf(eqA.y + edv[1]) - mx[1]); z[1] += wA1; }
        if (H > 2) { wA2 = __expf(leakyf(eqA.z + edv[2]) - mx[2]); z[2] += wA2; }
        float wB0 = __expf(leakyf(eqB.x + edv[0]) - mx[0]); z[0] += wB0;
        float wB1 = wB0, wB2 = wB0;
        if (H > 1) { wB1 = __expf(leakyf(eqB.y + edv[1]) - mx[1]); z[1] += wB1; }
        if (H > 2) { wB2 = __expf(leakyf(eqB.z + edv[2]) - mx[2]); z[2] += wB2; }
#pragma unroll
        for (int i = 0; i < NI; i++) {
            int j = lane + 32 * i;
            if (j < M) {
                int hdi = j / O;
                float wsA = (H == 1) ? wA0 : (hdi == 0 ? wA0 : (hdi == 1 ? wA1 : wA2));
                float wsB = (H == 1) ? wB0 : (hdi == 0 ? wB0 : (hdi == 1 ? wB1 : wB2));
                acc[i] += wsA * fA[i];
                acc[i] += wsB * fB[i];
            }
        }
    }
    if (e < end) {  // tail edge
        int s = __ldg(&g_col[e]);
        const float* hs = g_h + (size_t)s * SIN;
        float4 eq = __ldg((const float4*)(hs + ESOFF));
        float w0 = __expf(leakyf(eq.x + edv[0]) - mx[0]); z[0] += w0;
        float w1 = w0, w2 = w0;
        if (H > 1) { w1 = __expf(leakyf(eq.y + edv[1]) - mx[1]); z[1] += w1; }
        if (H > 2) { w2 = __expf(leakyf(eq.z + edv[2]) - mx[2]); z[2] += w2; }
#pragma unroll
        for (int i = 0; i < NI; i++) {
            int j = lane + 32 * i;
            if (j < M) {
                int hdi = j / O;
                float ws = (H == 1) ? w0 : (hdi == 0 ? w0 : (hdi == 1 ? w1 : w2));
                acc[i] += ws * __ldg(&hs[j]);
            }
        }
    }
    if (!FUSEPOOL) {
#pragma unroll
        for (int i = 0; i < NI; i++) {
            int j = lane + 32 * i;
            if (j < M) {
                int hdi = j / O;
                float zz = (H == 1) ? z[0] : (hdi == 0 ? z[0] : (hdi == 1 ? z[1] : z[2]));
                float v = acc[i] / (zz + 1e-16f) + __ldg(&bias[j]);
                if (ACT) v = leakyf(v);
                g_act[(size_t)n * SOUT + j] = v;
            }
        }
    } else {
        // layer 2 (H==1, M==128): stage in shared, transpose to float4, vector-atomic into pool
        int b = __ldg(&batch[n]);
#pragma unroll
        for (int i = 0; i < NI; i++) {
            int j = lane + 32 * i;
            if (j < M) {
                float v = acc[i] / (z[0] + 1e-16f) + __ldg(&bias[j]);
                sh[wid][j] = v;
            }
        }
        __syncwarp();
        float4 vv = *(float4*)&sh[wid][lane * 4];
        atomicAdd(reinterpret_cast<float4*>(g_pool + b * 128) + lane, vv);
        if (lane == 0) atomicAdd(&g_cnt[b], 1);
    }
}

__global__ void finalize_kernel(float* __restrict__ out) {
    int b = blockIdx.x, j = threadIdx.x;  // 256 threads
    if (j < 128) {
        int c = g_cnt[b];
        float cf = (float)(c > 1 ? c : 1);
        out[b * 256 + j] = g_pool[b * 128 + j] / cf;
    } else {
        out[b * 256 + j] = 0.f;  // zero loc half for atomic accumulation
    }
}

// ---------------- location MLP: 4 blocks per graph, atomic accumulate ----------------
__global__ void locmlp_kernel(const float* __restrict__ loc, const float* __restrict__ Wl1,
                              const float* __restrict__ bl1, const float* __restrict__ Wl2,
                              const float* __restrict__ bl2, float* __restrict__ out) {
    int b = blockIdx.x >> 2;
    int part = blockIdx.x & 3;
    int t = threadIdx.x;  // 256
    int lbeg = part * 12 + min(part, 2);
    int lend = (part + 1) * 12 + min(part + 1, 2);
    __shared__ float hid[256];
    float w1a = __ldg(&Wl1[t]), w1b = __ldg(&Wl1[256 + t]), b1v = __ldg(&bl1[t]);
    float accv = 0.f;
    for (int l = lbeg; l < lend; l++) {
        float lx = __ldg(&loc[(b * NLOCS + l) * 2 + 0]);
        float ly = __ldg(&loc[(b * NLOCS + l) * 2 + 1]);
        float hv = tanhf(lx * w1a + ly * w1b + b1v);
        __syncthreads();
        hid[t] = hv;
        __syncthreads();
        if (t < 128) {
            float s = 0.f;
#pragma unroll 8
            for (int k = 0; k < 256; k++) s += hid[k] * __ldg(&Wl2[k * 128 + t]);
            accv += s;
        }
    }
    if (t < 128) {
        float v = accv * (1.f / (float)NLOCS);
        if (part == 0) v += __ldg(&bl2[t]);
        atomicAdd(&out[b * 256 + 128 + t], v);
    }
}

// ---------------- launch ----------------
extern "C" void kernel_launch(void* const* d_in, const int* in_sizes, int n_in,
                              void* d_out, int out_size) {
    const float* x   = (const float*)d_in[0];
    const float* loc = (const float*)d_in[1];
    const int* ei    = (const int*)d_in[2];
    const int* batch = (const int*)d_in[3];
    const float* W0  = (const float*)d_in[4];
    const float* as0 = (const float*)d_in[5];
    const float* ad0 = (const float*)d_in[6];
    const float* b0  = (const float*)d_in[7];
    const float* W1  = (const float*)d_in[8];
    const float* as1 = (const float*)d_in[9];
    const float* ad1 = (const float*)d_in[10];
    const float* b1  = (const float*)d_in[11];
    const float* W2  = (const float*)d_in[12];
    const float* as2 = (const float*)d_in[13];
    const float* ad2 = (const float*)d_in[14];
    const float* b2  = (const float*)d_in[15];
    const float* Wl1 = (const float*)d_in[16];
    const float* bl1 = (const float*)d_in[17];
    const float* Wl2 = (const float*)d_in[18];
    const float* bl2 = (const float*)d_in[19];
    float* out = (float*)d_out;
    const int* srcv = ei;
    const int* dstv = ei + NEDGES;

    pack_weights<<<(8 * 144 + 255) / 256, 256>>>(W0, as0, ad0, 0, 6, 129, 144, 8, 3, 43, 132, 136);
    pack_weights<<<(132 * 144 + 255) / 256, 256>>>(W1, as1, ad1, 1, 129, 129, 144, 132, 3, 43, 132, 136);
    pack_weights<<<(132 * 132 + 255) / 256, 256>>>(W2, as2, ad2, 2, 129, 128, 132, 132, 1, 128, 128, 129);

    int nscan = (NNODES + 1023) / 1024;  // 49
    zero_aux<<<(NNODES + 255) / 256, 256>>>();
    hist_kernel<<<(NEDGES + 255) / 256, 256>>>(dstv);
    scan_blocks<<<nscan, 1024>>>();
    scan_tops<<<1, 64>>>(nscan);
    scan_add<<<nscan, 1024>>>();
    fill_kernel<<<(NEDGES + 255) / 256, 256>>>(srcv, dstv);

    int gatherBlocks = (NNODES + 7) / 8;
    int gemmBlocks = (NNODES + 63) / 64;

    gemm0_kernel<<<NNODES, 160>>>(x);
    gather_kernel<3, 43, 129, 144, 132, 136, 132, 1, 0><<<gatherBlocks, 256>>>(b0, batch);
    gemm_tiled<144><<<gemmBlocks, dim3(36, 8)>>>(1, NNODES);
    gather_kernel<3, 43, 129, 144, 132, 136, 132, 1, 0><<<gatherBlocks, 256>>>(b1, batch);
    gemm_tiled<132><<<gemmBlocks, dim3(33, 8)>>>(2, NNODES);
    gather_kernel<1, 128, 128, 132, 128, 129, 128, 0, 1><<<gatherBlocks, 256>>>(b2, batch);

    finalize_kernel<<<64, 256>>>(out);
    locmlp_kernel<<<256, 256>>>(loc, Wl1, bl1, Wl2, bl2, out);
}